// round 3
// baseline (speedup 1.0000x reference)
#include <cuda_runtime.h>

#define NPTS 32768
#define KNB  64
#define CDIM 256
#define PAIR 32
#define HID  64
#define BINS 16
#define CLIPV 32
#define LN_EPS 1e-5f

// Scratch for projection results (allocation-free rule -> __device__ globals)
__device__ float g_left[NPTS * PAIR];    // 4 MB
__device__ float g_right[NPTS * PAIR];   // 4 MB

// ---------------------------------------------------------------------------
// Kernel 1: left = feat @ W_left, right = feat @ W_right  (fused as 64 cols)
// Tiled register-blocked GEMM: 64x64 output tile, 256 threads, 4x4 per thread.
// ---------------------------------------------------------------------------
__global__ __launch_bounds__(256) void proj_kernel(
    const float* __restrict__ feat,
    const float* __restrict__ Wl,
    const float* __restrict__ Wr)
{
    __shared__ float As[32][68];   // [c-chunk][row]  (68: 272B row stride, 16B aligned)
    __shared__ float Bs[32][64];   // [c-chunk][outcol]

    const int t   = threadIdx.x;
    const int tx  = t & 15;
    const int ty  = t >> 4;
    const int row0 = blockIdx.x * 64;

    float acc[4][4];
#pragma unroll
    for (int i = 0; i < 4; i++)
#pragma unroll
        for (int j = 0; j < 4; j++) acc[i][j] = 0.0f;

    const int lc   = t & 31;   // c within chunk (coalesced global read)
    const int lr   = t >> 5;   // 0..7
    const int bcol = t & 63;
    const int bk0  = t >> 6;   // 0..3

    for (int cb = 0; cb < CDIM; cb += 32) {
#pragma unroll
        for (int it = 0; it < 8; it++)
            As[lc][lr + it * 8] = feat[(size_t)(row0 + lr + it * 8) * CDIM + cb + lc];
#pragma unroll
        for (int it = 0; it < 8; it++) {
            int kk = bk0 + it * 4;
            Bs[kk][bcol] = (bcol < PAIR) ? Wl[(cb + kk) * PAIR + bcol]
                                         : Wr[(cb + kk) * PAIR + (bcol - PAIR)];
        }
        __syncthreads();
#pragma unroll
        for (int kk = 0; kk < 32; kk++) {
            float4 a4 = *(const float4*)&As[kk][ty * 4];
            float4 b4 = *(const float4*)&Bs[kk][tx * 4];
            float av[4] = {a4.x, a4.y, a4.z, a4.w};
            float bv[4] = {b4.x, b4.y, b4.z, b4.w};
#pragma unroll
            for (int i = 0; i < 4; i++)
#pragma unroll
                for (int j = 0; j < 4; j++)
                    acc[i][j] = fmaf(av[i], bv[j], acc[i][j]);
        }
        __syncthreads();
    }

#pragma unroll
    for (int i = 0; i < 4; i++) {
        int row = row0 + ty * 4 + i;
#pragma unroll
        for (int j = 0; j < 4; j++) {
            int col = tx * 4 + j;
            if (col < PAIR) g_left[row * PAIR + col] = acc[i][j];
            else            g_right[row * PAIR + (col - PAIR)] = acc[i][j];
        }
    }
}

// ---------------------------------------------------------------------------
// Kernel 2: per-pair pipeline. 1 thread = 1 (n,k) pair. Block of 256 = 4 n's.
// dcode[32] in registers; W1 transposed + W2 in SMEM (broadcast LDS.128).
// ---------------------------------------------------------------------------
__global__ __launch_bounds__(256) void pair_kernel(
    const int*   __restrict__ resi,
    const int*   __restrict__ chain,
    const int*   __restrict__ batch,
    const int*   __restrict__ neigh,
    const float* __restrict__ Wpos,
    const float* __restrict__ lns,
    const float* __restrict__ lnb,
    const float* __restrict__ W1,
    const float* __restrict__ b1,
    const float* __restrict__ W2,
    const float* __restrict__ b2,
    float* __restrict__ out_logp,
    float* __restrict__ out_dmap)
{
    __shared__ float sW1t[HID][PAIR];       // [j][i] transposed -> float4 over i
    __shared__ float sW2[HID][BINS];        // [j][b]
    __shared__ float sWpos[2 * CLIPV + 1][PAIR];
    __shared__ float sb1[HID], sb2[BINS], slns[PAIR], slnb[PAIR];
    __shared__ float sleft[4][PAIR];
    __shared__ int   sresi[4], schain[4], sbatch[4];

    const int t = threadIdx.x;

    for (int idx = t; idx < HID * PAIR; idx += 256) {
        int i = idx & (PAIR - 1);
        int j = idx >> 5;
        sW1t[j][i] = W1[i * HID + j];
    }
    for (int idx = t; idx < HID * BINS; idx += 256)
        sW2[idx >> 4][idx & 15] = W2[idx];
    for (int idx = t; idx < (2 * CLIPV + 1) * PAIR; idx += 256)
        sWpos[idx >> 5][idx & 31] = Wpos[idx];
    if (t < HID)  sb1[t] = b1[t];
    if (t < BINS) sb2[t] = b2[t];
    if (t < PAIR) { slns[t] = lns[t]; slnb[t] = lnb[t]; }

    const int nrow = t >> 6;       // 0..3
    const int k    = t & 63;
    const int n    = blockIdx.x * 4 + nrow;
    if (k < PAIR) sleft[nrow][k] = g_left[n * PAIR + k];
    if (k == 0) { sresi[nrow] = resi[n]; schain[nrow] = chain[n]; sbatch[nrow] = batch[n]; }
    __syncthreads();

    const int nb = neigh[n * KNB + k];           // coalesced
    int dr = resi[nb] - sresi[nrow];
    dr = min(max(dr, -CLIPV), CLIPV) + CLIPV;
    const bool same = (chain[nb] == schain[nrow]) && (batch[nb] == sbatch[nrow]);

    // ---- dcode = left[n] + right[nb] (+ Wpos[rel] if same) ----
    float d[PAIR];
    const float4* r4 = (const float4*)&g_right[(size_t)nb * PAIR];
#pragma unroll
    for (int i4 = 0; i4 < PAIR / 4; i4++) {
        float4 r = r4[i4];                       // L2-resident gather
        d[i4 * 4 + 0] = r.x; d[i4 * 4 + 1] = r.y;
        d[i4 * 4 + 2] = r.z; d[i4 * 4 + 3] = r.w;
    }
#pragma unroll
    for (int i = 0; i < PAIR; i++) d[i] += sleft[nrow][i];
    if (same) {
#pragma unroll
        for (int i = 0; i < PAIR; i++) d[i] += sWpos[dr][i];
    }

    // ---- LayerNorm over 32 ----
    float mu = 0.0f;
#pragma unroll
    for (int i = 0; i < PAIR; i++) mu += d[i];
    mu *= (1.0f / PAIR);
    float var = 0.0f;
#pragma unroll
    for (int i = 0; i < PAIR; i++) { float e = d[i] - mu; var = fmaf(e, e, var); }
    var *= (1.0f / PAIR);
    const float rs = rsqrtf(var + LN_EPS);
#pragma unroll
    for (int i = 0; i < PAIR; i++)
        d[i] = fmaf((d[i] - mu) * rs, slns[i], slnb[i]);

    // ---- MLP: 32 -> 64 (gelu-tanh) -> 16 ----
    float lg[BINS];
#pragma unroll
    for (int b = 0; b < BINS; b++) lg[b] = sb2[b];

#pragma unroll 8
    for (int j = 0; j < HID; j++) {
        float a = sb1[j];
#pragma unroll
        for (int i4 = 0; i4 < PAIR / 4; i4++) {
            float4 w = *(const float4*)&sW1t[j][i4 * 4];   // broadcast LDS.128
            a = fmaf(d[i4 * 4 + 0], w.x, a);
            a = fmaf(d[i4 * 4 + 1], w.y, a);
            a = fmaf(d[i4 * 4 + 2], w.z, a);
            a = fmaf(d[i4 * 4 + 3], w.w, a);
        }
        // gelu(x) approx-tanh == x * sigmoid(2*sqrt(2/pi)*(x + 0.044715 x^3))
        float x3 = a * a * a;
        float ye = fmaf(-0.0713548163f, x3, -1.5957691216f * a);
        float h  = __fdividef(a, 1.0f + __expf(ye));
#pragma unroll
        for (int b4 = 0; b4 < BINS / 4; b4++) {
            float4 w = *(const float4*)&sW2[j][b4 * 4];    // broadcast LDS.128
            lg[b4 * 4 + 0] = fmaf(h, w.x, lg[b4 * 4 + 0]);
            lg[b4 * 4 + 1] = fmaf(h, w.y, lg[b4 * 4 + 1]);
            lg[b4 * 4 + 2] = fmaf(h, w.z, lg[b4 * 4 + 2]);
            lg[b4 * 4 + 3] = fmaf(h, w.w, lg[b4 * 4 + 3]);
        }
    }

    // ---- log_softmax + expected distance ----
    float m = lg[0];
#pragma unroll
    for (int b = 1; b < BINS; b++) m = fmaxf(m, lg[b]);
    float s = 0.0f, ws = 0.0f;
#pragma unroll
    for (int b = 0; b < BINS; b++) {
        float e = __expf(lg[b] - m);
        s += e;
        ws = fmaf(e, ((float)b + 0.5f) * 1.375f, ws);   // bin centers, step 22/16
    }
    const float ls = __logf(s);

    const size_t pidx = (size_t)(n * KNB + k);
    float* op = out_logp + pidx * BINS;
#pragma unroll
    for (int b4 = 0; b4 < BINS / 4; b4++) {
        float4 o;
        o.x = lg[b4 * 4 + 0] - m - ls;
        o.y = lg[b4 * 4 + 1] - m - ls;
        o.z = lg[b4 * 4 + 2] - m - ls;
        o.w = lg[b4 * 4 + 3] - m - ls;
        *(float4*)(op + b4 * 4) = o;
    }
    out_dmap[pidx] = __fdividef(ws, s);
}

// ---------------------------------------------------------------------------
extern "C" void kernel_launch(void* const* d_in, const int* in_sizes, int n_in,
                              void* d_out, int out_size)
{
    const float* feat  = (const float*)d_in[0];
    const int*   resi  = (const int*)  d_in[1];
    const int*   chain = (const int*)  d_in[2];
    const int*   batch = (const int*)  d_in[3];
    const int*   neigh = (const int*)  d_in[4];
    const float* Wl    = (const float*)d_in[5];
    const float* Wr    = (const float*)d_in[6];
    const float* Wpos  = (const float*)d_in[7];
    const float* lns   = (const float*)d_in[8];
    const float* lnb   = (const float*)d_in[9];
    const float* W1    = (const float*)d_in[10];
    const float* b1    = (const float*)d_in[11];
    const float* W2    = (const float*)d_in[12];
    const float* b2    = (const float*)d_in[13];

    float* out_logp = (float*)d_out;
    float* out_dmap = (float*)d_out + (size_t)NPTS * KNB * BINS;

    proj_kernel<<<NPTS / 64, 256>>>(feat, Wl, Wr);
    pair_kernel<<<NPTS / 4, 256>>>(resi, chain, batch, neigh, Wpos, lns, lnb,
                                   W1, b1, W2, b2, out_logp, out_dmap);
}

// round 6
// speedup vs baseline: 1.6248x; 1.6248x over previous
#include <cuda_runtime.h>

#define NPTS 32768
#define KNB  64
#define CDIM 256
#define PAIR 32
#define HID  64
#define BINS 16
#define CLIPV 32
#define LN_EPS 1e-5f
#define PMUX 4            // pairs per thread
#define TPB  128          // threads per block -> 512 pairs = 8 n's per block

typedef unsigned long long u64;

// Scratch for projection results (allocation-free rule -> __device__ globals)
static __device__ float g_left[NPTS * PAIR];    // 4 MB
static __device__ float g_right[NPTS * PAIR];   // 4 MB

// ---------------- packed f32x2 helpers (FFMA2: PTX-only on sm_103a) --------
__device__ __forceinline__ u64 pk2(float lo, float hi) {
    u64 r; asm("mov.b64 %0,{%1,%2};" : "=l"(r) : "f"(lo), "f"(hi)); return r;
}
__device__ __forceinline__ float2 upk2(u64 v) {
    float2 f; asm("mov.b64 {%0,%1},%2;" : "=f"(f.x), "=f"(f.y) : "l"(v)); return f;
}
__device__ __forceinline__ u64 f2fma(u64 a, u64 b, u64 c) {
    u64 r; asm("fma.rn.f32x2 %0,%1,%2,%3;" : "=l"(r) : "l"(a), "l"(b), "l"(c)); return r;
}
__device__ __forceinline__ u64 f2add(u64 a, u64 b) {
    u64 r; asm("add.rn.f32x2 %0,%1,%2;" : "=l"(r) : "l"(a), "l"(b)); return r;
}
__device__ __forceinline__ u64 f2mul(u64 a, u64 b) {
    u64 r; asm("mul.rn.f32x2 %0,%1,%2;" : "=l"(r) : "l"(a), "l"(b)); return r;
}

// ---------------------------------------------------------------------------
// Kernel 1: left = feat @ W_left, right = feat @ W_right  (fused as 64 cols)
// ---------------------------------------------------------------------------
__global__ __launch_bounds__(256) void proj_kernel(
    const float* __restrict__ feat,
    const float* __restrict__ Wl,
    const float* __restrict__ Wr)
{
    __shared__ float As[32][68];
    __shared__ float Bs[32][64];

    const int t   = threadIdx.x;
    const int tx  = t & 15;
    const int ty  = t >> 4;
    const int row0 = blockIdx.x * 64;

    float acc[4][4];
#pragma unroll
    for (int i = 0; i < 4; i++)
#pragma unroll
        for (int j = 0; j < 4; j++) acc[i][j] = 0.0f;

    const int lc   = t & 31;
    const int lr   = t >> 5;
    const int bcol = t & 63;
    const int bk0  = t >> 6;

    for (int cb = 0; cb < CDIM; cb += 32) {
#pragma unroll
        for (int it = 0; it < 8; it++)
            As[lc][lr + it * 8] = feat[(size_t)(row0 + lr + it * 8) * CDIM + cb + lc];
#pragma unroll
        for (int it = 0; it < 8; it++) {
            int kk = bk0 + it * 4;
            Bs[kk][bcol] = (bcol < PAIR) ? Wl[(cb + kk) * PAIR + bcol]
                                         : Wr[(cb + kk) * PAIR + (bcol - PAIR)];
        }
        __syncthreads();
#pragma unroll
        for (int kk = 0; kk < 32; kk++) {
            float4 a4 = *(const float4*)&As[kk][ty * 4];
            float4 b4 = *(const float4*)&Bs[kk][tx * 4];
            float av[4] = {a4.x, a4.y, a4.z, a4.w};
            float bv[4] = {b4.x, b4.y, b4.z, b4.w};
#pragma unroll
            for (int i = 0; i < 4; i++)
#pragma unroll
                for (int j = 0; j < 4; j++)
                    acc[i][j] = fmaf(av[i], bv[j], acc[i][j]);
        }
        __syncthreads();
    }

#pragma unroll
    for (int i = 0; i < 4; i++) {
        int row = row0 + ty * 4 + i;
#pragma unroll
        for (int j = 0; j < 4; j++) {
            int col = tx * 4 + j;
            if (col < PAIR) g_left[row * PAIR + col] = acc[i][j];
            else            g_right[row * PAIR + (col - PAIR)] = acc[i][j];
        }
    }
}

// ---------------------------------------------------------------------------
// Kernel 2: per-pair pipeline, 4 pairs per thread, packed f32x2 math.
// Weights staged in SMEM pre-packed as f32x2 (ulonglong2 LDS.128, no movs).
// ---------------------------------------------------------------------------
__global__ __launch_bounds__(TPB, 2) void pair_kernel(
    const int*   __restrict__ resi,
    const int*   __restrict__ chain,
    const int*   __restrict__ batch,
    const int*   __restrict__ neigh,
    const float* __restrict__ Wpos,
    const float* __restrict__ lns,
    const float* __restrict__ lnb,
    const float* __restrict__ W1,
    const float* __restrict__ b1,
    const float* __restrict__ W2,
    const float* __restrict__ b2,
    float* __restrict__ out_logp,
    float* __restrict__ out_dmap)
{
    __shared__ __align__(16) u64 sW1p[HID][PAIR / 2];          // [j][i2], transposed, packed
    __shared__ __align__(16) u64 sW2p[HID][BINS / 2];          // [j][b2], packed
    __shared__ __align__(16) u64 sWposp[2 * CLIPV + 1][PAIR / 2];
    __shared__ __align__(16) u64 sleft[8][PAIR / 2];
    __shared__ u64 sln2[PAIR / 2], slnb2[PAIR / 2], sb2p[BINS / 2];
    __shared__ float sb1[HID];
    __shared__ int sres[8], sch[8], sba[8];

    const int t = threadIdx.x;

    for (int idx = t; idx < HID * (PAIR / 2); idx += TPB) {
        int i2 = idx & 15, j = idx >> 4;
        sW1p[j][i2] = pk2(W1[(2 * i2) * HID + j], W1[(2 * i2 + 1) * HID + j]);
    }
    for (int idx = t; idx < HID * (BINS / 2); idx += TPB) {
        int b2i = idx & 7, j = idx >> 3;
        sW2p[j][b2i] = pk2(W2[j * BINS + 2 * b2i], W2[j * BINS + 2 * b2i + 1]);
    }
    for (int idx = t; idx < (2 * CLIPV + 1) * (PAIR / 2); idx += TPB) {
        int i2 = idx & 15, r = idx >> 4;
        sWposp[r][i2] = pk2(Wpos[r * PAIR + 2 * i2], Wpos[r * PAIR + 2 * i2 + 1]);
    }
    {   // left codes for this block's 8 n's: exactly 128 packed entries
        int nloc = t >> 4, i2 = t & 15;
        int n = blockIdx.x * 8 + nloc;
        sleft[nloc][i2] = pk2(g_left[n * PAIR + 2 * i2], g_left[n * PAIR + 2 * i2 + 1]);
    }
    if (t < PAIR / 2) { sln2[t] = pk2(lns[2 * t], lns[2 * t + 1]);
                        slnb2[t] = pk2(lnb[2 * t], lnb[2 * t + 1]); }
    if (t < BINS / 2) sb2p[t] = pk2(b2[2 * t], b2[2 * t + 1]);
    if (t < HID)      sb1[t] = b1[t];
    if (t < 8) { int n = blockIdx.x * 8 + t;
                 sres[t] = resi[n]; sch[t] = chain[n]; sba[t] = batch[n]; }
    __syncthreads();

    const int pid0 = blockIdx.x * (TPB * PMUX) + t;
    int pid[PMUX];
    u64 d2[PMUX][PAIR / 2];

    // ---- gather + combine + LayerNorm (per pair) ----
#pragma unroll
    for (int p = 0; p < PMUX; p++) {
        pid[p] = pid0 + p * TPB;
        const int nloc = (t + p * TPB) >> 6;          // 0..7
        const int nb = neigh[pid[p]];                 // coalesced

        const ulonglong2* rrow = (const ulonglong2*)&g_right[(size_t)nb * PAIR];
#pragma unroll
        for (int q = 0; q < 8; q++) {
            ulonglong2 v = rrow[q];                   // L2-resident gather
            d2[p][2 * q] = v.x; d2[p][2 * q + 1] = v.y;
        }
#pragma unroll
        for (int i = 0; i < PAIR / 2; i++) d2[p][i] = f2add(d2[p][i], sleft[nloc][i]);

        int dr = resi[nb] - sres[nloc];
        dr = min(max(dr, -CLIPV), CLIPV) + CLIPV;
        if ((chain[nb] == sch[nloc]) && (batch[nb] == sba[nloc])) {
#pragma unroll
            for (int i = 0; i < PAIR / 2; i++) d2[p][i] = f2add(d2[p][i], sWposp[dr][i]);
        }

        // LayerNorm over 32 (packed)
        u64 s2 = d2[p][0];
#pragma unroll
        for (int i = 1; i < PAIR / 2; i++) s2 = f2add(s2, d2[p][i]);
        float2 sf = upk2(s2);
        const float mu = (sf.x + sf.y) * (1.0f / PAIR);
        const u64 nmu2 = pk2(-mu, -mu);
        u64 v2 = 0;
#pragma unroll
        for (int i = 0; i < PAIR / 2; i++) {
            u64 e = f2add(d2[p][i], nmu2);
            v2 = f2fma(e, e, v2);
            d2[p][i] = e;
        }
        float2 vf = upk2(v2);
        const float rs = rsqrtf((vf.x + vf.y) * (1.0f / PAIR) + LN_EPS);
        const u64 rs2 = pk2(rs, rs);
#pragma unroll
        for (int i = 0; i < PAIR / 2; i++)
            d2[p][i] = f2fma(f2mul(d2[p][i], rs2), sln2[i], slnb2[i]);
    }

    // ---- MLP: 32 -> 64 (gelu) -> 16, packed FFMA2, weights amortized x4 ----
    u64 lg2[PMUX][BINS / 2];
#pragma unroll
    for (int p = 0; p < PMUX; p++)
#pragma unroll
        for (int b = 0; b < BINS / 2; b++) lg2[p][b] = sb2p[b];

#pragma unroll 2
    for (int j = 0; j < HID; j++) {
        u64 acc[PMUX] = {0, 0, 0, 0};
        const ulonglong2* w1r = (const ulonglong2*)sW1p[j];
#pragma unroll
        for (int q = 0; q < 8; q++) {
            ulonglong2 w = w1r[q];                    // broadcast LDS.128, pre-packed
#pragma unroll
            for (int p = 0; p < PMUX; p++) {
                acc[p] = f2fma(d2[p][2 * q], w.x, acc[p]);
                acc[p] = f2fma(d2[p][2 * q + 1], w.y, acc[p]);
            }
        }
        const float bj = sb1[j];
        u64 hp[PMUX];
#pragma unroll
        for (int p = 0; p < PMUX; p++) {
            float2 af = upk2(acc[p]);
            float a = af.x + af.y + bj;
            // gelu-tanh == a * sigmoid(1.5957692*(a + 0.044715 a^3))
            float x3 = a * a * a;
            float ye = fmaf(-0.0713548163f, x3, -1.5957691216f * a);
            float h = __fdividef(a, 1.0f + __expf(ye));
            hp[p] = pk2(h, h);
        }
        const ulonglong2* w2r = (const ulonglong2*)sW2p[j];
#pragma unroll
        for (int q = 0; q < 4; q++) {
            ulonglong2 w = w2r[q];                    // broadcast LDS.128, pre-packed
#pragma unroll
            for (int p = 0; p < PMUX; p++) {
                lg2[p][2 * q]     = f2fma(hp[p], w.x, lg2[p][2 * q]);
                lg2[p][2 * q + 1] = f2fma(hp[p], w.y, lg2[p][2 * q + 1]);
            }
        }
    }

    // ---- log_softmax + expected distance + store ----
#pragma unroll
    for (int p = 0; p < PMUX; p++) {
        float l[BINS];
#pragma unroll
        for (int b = 0; b < BINS / 2; b++) {
            float2 f = upk2(lg2[p][b]);
            l[2 * b] = f.x; l[2 * b + 1] = f.y;
        }
        float m = l[0];
#pragma unroll
        for (int b = 1; b < BINS; b++) m = fmaxf(m, l[b]);
        float s = 0.0f, ws = 0.0f;
#pragma unroll
        for (int b = 0; b < BINS; b++) {
            float e = __expf(l[b] - m);
            s += e;
            ws = fmaf(e, ((float)b + 0.5f) * 1.375f, ws);
        }
        const float ls = __logf(s);

        float* op = out_logp + (size_t)pid[p] * BINS;
#pragma unroll
        for (int b4 = 0; b4 < BINS / 4; b4++) {
            float4 o;
            o.x = l[b4 * 4 + 0] - m - ls;
            o.y = l[b4 * 4 + 1] - m - ls;
            o.z = l[b4 * 4 + 2] - m - ls;
            o.w = l[b4 * 4 + 3] - m - ls;
            *(float4*)(op + b4 * 4) = o;
        }
        out_dmap[pid[p]] = __fdividef(ws, s);
    }
}

// ---------------------------------------------------------------------------
extern "C" void kernel_launch(void* const* d_in, const int* in_sizes, int n_in,
                              void* d_out, int out_size)
{
    const float* feat  = (const float*)d_in[0];
    const int*   resi  = (const int*)  d_in[1];
    const int*   chain = (const int*)  d_in[2];
    const int*   batch = (const int*)  d_in[3];
    const int*   neigh = (const int*)  d_in[4];
    const float* Wl    = (const float*)d_in[5];
    const float* Wr    = (const float*)d_in[6];
    const float* Wpos  = (const float*)d_in[7];
    const float* lns   = (const float*)d_in[8];
    const float* lnb   = (const float*)d_in[9];
    const float* W1    = (const float*)d_in[10];
    const float* b1    = (const float*)d_in[11];
    const float* W2    = (const float*)d_in[12];
    const float* b2    = (const float*)d_in[13];

    float* out_logp = (float*)d_out;
    float* out_dmap = (float*)d_out + (size_t)NPTS * KNB * BINS;

    proj_kernel<<<NPTS / 64, 256>>>(feat, Wl, Wr);
    pair_kernel<<<(NPTS * KNB) / (TPB * PMUX), TPB>>>(resi, chain, batch, neigh,
                                                      Wpos, lns, lnb, W1, b1, W2, b2,
                                                      out_logp, out_dmap);
}

// round 7
// speedup vs baseline: 1.7054x; 1.0496x over previous
#include <cuda_runtime.h>

#define NPTS 32768
#define KNB  64
#define CDIM 256
#define PAIR 32
#define HID  64
#define BINS 16
#define CLIPV 32
#define LN_EPS 1e-5f
#define PMUX 4            // pairs per thread
#define TPB  128          // threads per block -> 512 pairs = 8 n's per block

typedef unsigned long long u64;

// Scratch for projection results (allocation-free rule -> __device__ globals)
static __device__ float g_left[NPTS * PAIR];    // 4 MB
static __device__ float g_right[NPTS * PAIR];   // 4 MB

// ---------------- packed f32x2 helpers (FFMA2: PTX-only on sm_103a) --------
__device__ __forceinline__ u64 pk2(float lo, float hi) {
    u64 r; asm("mov.b64 %0,{%1,%2};" : "=l"(r) : "f"(lo), "f"(hi)); return r;
}
__device__ __forceinline__ float2 upk2(u64 v) {
    float2 f; asm("mov.b64 {%0,%1},%2;" : "=f"(f.x), "=f"(f.y) : "l"(v)); return f;
}
__device__ __forceinline__ u64 f2fma(u64 a, u64 b, u64 c) {
    u64 r; asm("fma.rn.f32x2 %0,%1,%2,%3;" : "=l"(r) : "l"(a), "l"(b), "l"(c)); return r;
}
__device__ __forceinline__ u64 f2add(u64 a, u64 b) {
    u64 r; asm("add.rn.f32x2 %0,%1,%2;" : "=l"(r) : "l"(a), "l"(b)); return r;
}
__device__ __forceinline__ u64 f2mul(u64 a, u64 b) {
    u64 r; asm("mul.rn.f32x2 %0,%1,%2;" : "=l"(r) : "l"(a), "l"(b)); return r;
}
__device__ __forceinline__ float tanh_approx(float x) {
    float r; asm("tanh.approx.f32 %0,%1;" : "=f"(r) : "f"(x)); return r;
}

// ---------------------------------------------------------------------------
// Kernel 1: left = feat @ W_left, right = feat @ W_right  (fused as 64 cols)
// ---------------------------------------------------------------------------
__global__ __launch_bounds__(256) void proj_kernel(
    const float* __restrict__ feat,
    const float* __restrict__ Wl,
    const float* __restrict__ Wr)
{
    __shared__ float As[32][68];
    __shared__ float Bs[32][64];

    const int t   = threadIdx.x;
    const int tx  = t & 15;
    const int ty  = t >> 4;
    const int row0 = blockIdx.x * 64;

    float acc[4][4];
#pragma unroll
    for (int i = 0; i < 4; i++)
#pragma unroll
        for (int j = 0; j < 4; j++) acc[i][j] = 0.0f;

    const int lc   = t & 31;
    const int lr   = t >> 5;
    const int bcol = t & 63;
    const int bk0  = t >> 6;

    for (int cb = 0; cb < CDIM; cb += 32) {
#pragma unroll
        for (int it = 0; it < 8; it++)
            As[lc][lr + it * 8] = feat[(size_t)(row0 + lr + it * 8) * CDIM + cb + lc];
#pragma unroll
        for (int it = 0; it < 8; it++) {
            int kk = bk0 + it * 4;
            Bs[kk][bcol] = (bcol < PAIR) ? Wl[(cb + kk) * PAIR + bcol]
                                         : Wr[(cb + kk) * PAIR + (bcol - PAIR)];
        }
        __syncthreads();
#pragma unroll
        for (int kk = 0; kk < 32; kk++) {
            float4 a4 = *(const float4*)&As[kk][ty * 4];
            float4 b4 = *(const float4*)&Bs[kk][tx * 4];
            float av[4] = {a4.x, a4.y, a4.z, a4.w};
            float bv[4] = {b4.x, b4.y, b4.z, b4.w};
#pragma unroll
            for (int i = 0; i < 4; i++)
#pragma unroll
                for (int j = 0; j < 4; j++)
                    acc[i][j] = fmaf(av[i], bv[j], acc[i][j]);
        }
        __syncthreads();
    }

#pragma unroll
    for (int i = 0; i < 4; i++) {
        int row = row0 + ty * 4 + i;
#pragma unroll
        for (int j = 0; j < 4; j++) {
            int col = tx * 4 + j;
            if (col < PAIR) g_left[row * PAIR + col] = acc[i][j];
            else            g_right[row * PAIR + (col - PAIR)] = acc[i][j];
        }
    }
}

// ---------------------------------------------------------------------------
// Kernel 2: per-pair pipeline, 4 pairs per thread, packed f32x2 math.
// gelu via single MUFU.TANH; weights pre-packed f32x2 in SMEM.
// ---------------------------------------------------------------------------
__global__ __launch_bounds__(TPB, 2) void pair_kernel(
    const int*   __restrict__ resi,
    const int*   __restrict__ chain,
    const int*   __restrict__ batch,
    const int*   __restrict__ neigh,
    const float* __restrict__ Wpos,
    const float* __restrict__ lns,
    const float* __restrict__ lnb,
    const float* __restrict__ W1,
    const float* __restrict__ b1,
    const float* __restrict__ W2,
    const float* __restrict__ b2,
    float* __restrict__ out_logp,
    float* __restrict__ out_dmap)
{
    __shared__ __align__(16) u64 sW1p[HID][PAIR / 2];          // [j][i2], transposed, packed
    __shared__ __align__(16) u64 sW2p[HID][BINS / 2];          // [j][b2], packed
    __shared__ __align__(16) u64 sWposp[2 * CLIPV + 1][PAIR / 2];
    __shared__ __align__(16) u64 sleft[8][PAIR / 2];
    __shared__ u64 sln2[PAIR / 2], slnb2[PAIR / 2], sb2p[BINS / 2];
    __shared__ float sb1[HID];
    __shared__ int sres[8], sch[8], sba[8];

    const int t = threadIdx.x;

    for (int idx = t; idx < HID * (PAIR / 2); idx += TPB) {
        int i2 = idx & 15, j = idx >> 4;
        sW1p[j][i2] = pk2(W1[(2 * i2) * HID + j], W1[(2 * i2 + 1) * HID + j]);
    }
    for (int idx = t; idx < HID * (BINS / 2); idx += TPB) {
        int b2i = idx & 7, j = idx >> 3;
        sW2p[j][b2i] = pk2(W2[j * BINS + 2 * b2i], W2[j * BINS + 2 * b2i + 1]);
    }
    for (int idx = t; idx < (2 * CLIPV + 1) * (PAIR / 2); idx += TPB) {
        int i2 = idx & 15, r = idx >> 4;
        sWposp[r][i2] = pk2(Wpos[r * PAIR + 2 * i2], Wpos[r * PAIR + 2 * i2 + 1]);
    }
    {   // left codes for this block's 8 n's: exactly 128 packed entries
        int nloc = t >> 4, i2 = t & 15;
        int n = blockIdx.x * 8 + nloc;
        sleft[nloc][i2] = pk2(g_left[n * PAIR + 2 * i2], g_left[n * PAIR + 2 * i2 + 1]);
    }
    if (t < PAIR / 2) { sln2[t] = pk2(lns[2 * t], lns[2 * t + 1]);
                        slnb2[t] = pk2(lnb[2 * t], lnb[2 * t + 1]); }
    if (t < BINS / 2) sb2p[t] = pk2(b2[2 * t], b2[2 * t + 1]);
    if (t < HID)      sb1[t] = b1[t];
    if (t < 8) { int n = blockIdx.x * 8 + t;
                 sres[t] = resi[n]; sch[t] = chain[n]; sba[t] = batch[n]; }
    __syncthreads();

    const int pid0 = blockIdx.x * (TPB * PMUX) + t;
    int pid[PMUX];
    u64 d2[PMUX][PAIR / 2];

    // ---- gather + combine + LayerNorm (per pair) ----
#pragma unroll
    for (int p = 0; p < PMUX; p++) {
        pid[p] = pid0 + p * TPB;
        const int nloc = (t + p * TPB) >> 6;          // 0..7
        const int nb = neigh[pid[p]];                 // coalesced

        const ulonglong2* rrow = (const ulonglong2*)&g_right[(size_t)nb * PAIR];
#pragma unroll
        for (int q = 0; q < 8; q++) {
            ulonglong2 v = rrow[q];                   // L2-resident gather
            d2[p][2 * q] = v.x; d2[p][2 * q + 1] = v.y;
        }
#pragma unroll
        for (int i = 0; i < PAIR / 2; i++) d2[p][i] = f2add(d2[p][i], sleft[nloc][i]);

        int dr = resi[nb] - sres[nloc];
        dr = min(max(dr, -CLIPV), CLIPV) + CLIPV;
        if ((chain[nb] == sch[nloc]) && (batch[nb] == sba[nloc])) {
#pragma unroll
            for (int i = 0; i < PAIR / 2; i++) d2[p][i] = f2add(d2[p][i], sWposp[dr][i]);
        }

        // LayerNorm over 32 (packed)
        u64 s2 = d2[p][0];
#pragma unroll
        for (int i = 1; i < PAIR / 2; i++) s2 = f2add(s2, d2[p][i]);
        float2 sf = upk2(s2);
        const float mu = (sf.x + sf.y) * (1.0f / PAIR);
        const u64 nmu2 = pk2(-mu, -mu);
        u64 v2 = 0;
#pragma unroll
        for (int i = 0; i < PAIR / 2; i++) {
            u64 e = f2add(d2[p][i], nmu2);
            v2 = f2fma(e, e, v2);
            d2[p][i] = e;
        }
        float2 vf = upk2(v2);
        const float rs = rsqrtf((vf.x + vf.y) * (1.0f / PAIR) + LN_EPS);
        const u64 rs2 = pk2(rs, rs);
#pragma unroll
        for (int i = 0; i < PAIR / 2; i++)
            d2[p][i] = f2fma(f2mul(d2[p][i], rs2), sln2[i], slnb2[i]);
    }

    // ---- MLP: 32 -> 64 (gelu via MUFU.TANH) -> 16, packed FFMA2 ----
    u64 lg2[PMUX][BINS / 2];
#pragma unroll
    for (int p = 0; p < PMUX; p++)
#pragma unroll
        for (int b = 0; b < BINS / 2; b++) lg2[p][b] = sb2p[b];

#pragma unroll 4
    for (int j = 0; j < HID; j++) {
        u64 acc[PMUX] = {0, 0, 0, 0};
        const ulonglong2* w1r = (const ulonglong2*)sW1p[j];
#pragma unroll
        for (int q = 0; q < 8; q++) {
            ulonglong2 w = w1r[q];                    // broadcast LDS.128, pre-packed
#pragma unroll
            for (int p = 0; p < PMUX; p++) {
                acc[p] = f2fma(d2[p][2 * q], w.x, acc[p]);
                acc[p] = f2fma(d2[p][2 * q + 1], w.y, acc[p]);
            }
        }
        const float bj = sb1[j];
        u64 hp[PMUX];
#pragma unroll
        for (int p = 0; p < PMUX; p++) {
            float2 af = upk2(acc[p]);
            float a = af.x + af.y + bj;
            // gelu-tanh: 0.5a(1+tanh(0.7978845608(a + 0.044715 a^3)))
            float x2 = a * a;
            float u  = a * fmaf(0.0356774081f, x2, 0.7978845608f);
            float th = tanh_approx(u);                // single MUFU op
            float h  = 0.5f * fmaf(a, th, a);
            hp[p] = pk2(h, h);
        }
        const ulonglong2* w2r = (const ulonglong2*)sW2p[j];
#pragma unroll
        for (int q = 0; q < 4; q++) {
            ulonglong2 w = w2r[q];                    // broadcast LDS.128, pre-packed
#pragma unroll
            for (int p = 0; p < PMUX; p++) {
                lg2[p][2 * q]     = f2fma(hp[p], w.x, lg2[p][2 * q]);
                lg2[p][2 * q + 1] = f2fma(hp[p], w.y, lg2[p][2 * q + 1]);
            }
        }
    }

    // ---- log_softmax + expected distance + store (streaming) ----
#pragma unroll
    for (int p = 0; p < PMUX; p++) {
        float l[BINS];
#pragma unroll
        for (int b = 0; b < BINS / 2; b++) {
            float2 f = upk2(lg2[p][b]);
            l[2 * b] = f.x; l[2 * b + 1] = f.y;
        }
        float m = l[0];
#pragma unroll
        for (int b = 1; b < BINS; b++) m = fmaxf(m, l[b]);
        float s = 0.0f, ws = 0.0f;
#pragma unroll
        for (int b = 0; b < BINS; b++) {
            float e = __expf(l[b] - m);
            s += e;
            ws = fmaf(e, ((float)b + 0.5f) * 1.375f, ws);
        }
        const float ls = __logf(s);

        float* op = out_logp + (size_t)pid[p] * BINS;
#pragma unroll
        for (int b4 = 0; b4 < BINS / 4; b4++) {
            float4 o;
            o.x = l[b4 * 4 + 0] - m - ls;
            o.y = l[b4 * 4 + 1] - m - ls;
            o.z = l[b4 * 4 + 2] - m - ls;
            o.w = l[b4 * 4 + 3] - m - ls;
            __stcs((float4*)(op + b4 * 4), o);        // streaming: don't pollute L2
        }
        __stcs(out_dmap + pid[p], __fdividef(ws, s));
    }
}

// ---------------------------------------------------------------------------
extern "C" void kernel_launch(void* const* d_in, const int* in_sizes, int n_in,
                              void* d_out, int out_size)
{
    const float* feat  = (const float*)d_in[0];
    const int*   resi  = (const int*)  d_in[1];
    const int*   chain = (const int*)  d_in[2];
    const int*   batch = (const int*)  d_in[3];
    const int*   neigh = (const int*)  d_in[4];
    const float* Wl    = (const float*)d_in[5];
    const float* Wr    = (const float*)d_in[6];
    const float* Wpos  = (const float*)d_in[7];
    const float* lns   = (const float*)d_in[8];
    const float* lnb   = (const float*)d_in[9];
    const float* W1    = (const float*)d_in[10];
    const float* b1    = (const float*)d_in[11];
    const float* W2    = (const float*)d_in[12];
    const float* b2    = (const float*)d_in[13];

    float* out_logp = (float*)d_out;
    float* out_dmap = (float*)d_out + (size_t)NPTS * KNB * BINS;

    proj_kernel<<<NPTS / 64, 256>>>(feat, Wl, Wr);
    pair_kernel<<<(NPTS * KNB) / (TPB * PMUX), TPB>>>(resi, chain, batch, neigh,
                                                      Wpos, lns, lnb, W1, b1, W2, b2,
                                                      out_logp, out_dmap);
}

// round 8
// speedup vs baseline: 1.7140x; 1.0051x over previous
#include <cuda_runtime.h>

#define NPTS 32768
#define KNB  64
#define CDIM 256
#define PAIR 32
#define HID  64
#define BINS 16
#define CLIPV 32
#define LN_EPS 1e-5f
#define PMUX 4            // pairs per thread
#define TPB  128          // threads per block -> 512 pairs = 8 n's per block
#define LOG2E 1.4426950408889634f

typedef unsigned long long u64;

// Scratch (allocation-free rule -> __device__ globals)
static __device__ float g_left[NPTS * PAIR];    // 4 MB
static __device__ float g_right[NPTS * PAIR];   // 4 MB
static __device__ int2  g_meta[NPTS];           // (resi, chain<<16|batch)

// ---------------- packed f32x2 helpers (FFMA2: PTX-only on sm_103a) --------
__device__ __forceinline__ u64 pk2(float lo, float hi) {
    u64 r; asm("mov.b64 %0,{%1,%2};" : "=l"(r) : "f"(lo), "f"(hi)); return r;
}
__device__ __forceinline__ float2 upk2(u64 v) {
    float2 f; asm("mov.b64 {%0,%1},%2;" : "=f"(f.x), "=f"(f.y) : "l"(v)); return f;
}
__device__ __forceinline__ u64 f2fma(u64 a, u64 b, u64 c) {
    u64 r; asm("fma.rn.f32x2 %0,%1,%2,%3;" : "=l"(r) : "l"(a), "l"(b), "l"(c)); return r;
}
__device__ __forceinline__ u64 f2add(u64 a, u64 b) {
    u64 r; asm("add.rn.f32x2 %0,%1,%2;" : "=l"(r) : "l"(a), "l"(b)); return r;
}
__device__ __forceinline__ u64 f2mul(u64 a, u64 b) {
    u64 r; asm("mul.rn.f32x2 %0,%1,%2;" : "=l"(r) : "l"(a), "l"(b)); return r;
}
__device__ __forceinline__ float tanh_approx(float x) {
    float r; asm("tanh.approx.f32 %0,%1;" : "=f"(r) : "f"(x)); return r;
}
__device__ __forceinline__ float ex2f(float x) {
    float r; asm("ex2.approx.f32 %0,%1;" : "=f"(r) : "f"(x)); return r;
}

// ---------------------------------------------------------------------------
// Kernel 0: pack per-residue metadata into one 8-byte record
// ---------------------------------------------------------------------------
__global__ __launch_bounds__(256) void meta_kernel(
    const int* __restrict__ resi,
    const int* __restrict__ chain,
    const int* __restrict__ batch)
{
    int i = blockIdx.x * 256 + threadIdx.x;
    g_meta[i] = make_int2(resi[i], (chain[i] << 16) | batch[i]);
}

// ---------------------------------------------------------------------------
// Kernel 1: left = feat @ W_left, right = feat @ W_right  (fused as 64 cols)
// ---------------------------------------------------------------------------
__global__ __launch_bounds__(256) void proj_kernel(
    const float* __restrict__ feat,
    const float* __restrict__ Wl,
    const float* __restrict__ Wr)
{
    __shared__ float As[32][68];
    __shared__ float Bs[32][64];

    const int t   = threadIdx.x;
    const int tx  = t & 15;
    const int ty  = t >> 4;
    const int row0 = blockIdx.x * 64;

    float acc[4][4];
#pragma unroll
    for (int i = 0; i < 4; i++)
#pragma unroll
        for (int j = 0; j < 4; j++) acc[i][j] = 0.0f;

    const int lc   = t & 31;
    const int lr   = t >> 5;
    const int bcol = t & 63;
    const int bk0  = t >> 6;

    for (int cb = 0; cb < CDIM; cb += 32) {
#pragma unroll
        for (int it = 0; it < 8; it++)
            As[lc][lr + it * 8] = feat[(size_t)(row0 + lr + it * 8) * CDIM + cb + lc];
#pragma unroll
        for (int it = 0; it < 8; it++) {
            int kk = bk0 + it * 4;
            Bs[kk][bcol] = (bcol < PAIR) ? Wl[(cb + kk) * PAIR + bcol]
                                         : Wr[(cb + kk) * PAIR + (bcol - PAIR)];
        }
        __syncthreads();
#pragma unroll
        for (int kk = 0; kk < 32; kk++) {
            float4 a4 = *(const float4*)&As[kk][ty * 4];
            float4 b4 = *(const float4*)&Bs[kk][tx * 4];
            float av[4] = {a4.x, a4.y, a4.z, a4.w};
            float bv[4] = {b4.x, b4.y, b4.z, b4.w};
#pragma unroll
            for (int i = 0; i < 4; i++)
#pragma unroll
                for (int j = 0; j < 4; j++)
                    acc[i][j] = fmaf(av[i], bv[j], acc[i][j]);
        }
        __syncthreads();
    }

#pragma unroll
    for (int i = 0; i < 4; i++) {
        int row = row0 + ty * 4 + i;
#pragma unroll
        for (int j = 0; j < 4; j++) {
            int col = tx * 4 + j;
            if (col < PAIR) g_left[row * PAIR + col] = acc[i][j];
            else            g_right[row * PAIR + (col - PAIR)] = acc[i][j];
        }
    }
}

// ---------------------------------------------------------------------------
// Kernel 2: per-pair pipeline, 4 pairs/thread, packed f32x2 math.
// All gathers front-batched; meta packed; W2 pre-halved; bias in acc init.
// ---------------------------------------------------------------------------
__global__ __launch_bounds__(TPB, 2) void pair_kernel(
    const int*   __restrict__ neigh,
    const float* __restrict__ Wpos,
    const float* __restrict__ lns,
    const float* __restrict__ lnb,
    const float* __restrict__ W1,
    const float* __restrict__ b1,
    const float* __restrict__ W2,
    const float* __restrict__ b2,
    float* __restrict__ out_logp,
    float* __restrict__ out_dmap)
{
    __shared__ __align__(16) u64 sW1p[HID][PAIR / 2];          // [j][i2], transposed, packed
    __shared__ __align__(16) u64 sW2p[HID][BINS / 2];          // [j][b2], packed, pre-halved
    __shared__ __align__(16) u64 sWposp[2 * CLIPV + 1][PAIR / 2];
    __shared__ __align__(16) u64 sleft[8][PAIR / 2];
    __shared__ u64 sln2[PAIR / 2], slnb2[PAIR / 2], sb2p[BINS / 2];
    __shared__ float sb1[HID];
    __shared__ int sres[8], skey[8];

    const int t = threadIdx.x;

    for (int idx = t; idx < HID * (PAIR / 2); idx += TPB) {
        int i2 = idx & 15, j = idx >> 4;
        sW1p[j][i2] = pk2(W1[(2 * i2) * HID + j], W1[(2 * i2 + 1) * HID + j]);
    }
    for (int idx = t; idx < HID * (BINS / 2); idx += TPB) {
        int b2i = idx & 7, j = idx >> 3;
        sW2p[j][b2i] = pk2(0.5f * W2[j * BINS + 2 * b2i],
                           0.5f * W2[j * BINS + 2 * b2i + 1]);   // 0.5 of gelu folded in
    }
    for (int idx = t; idx < (2 * CLIPV + 1) * (PAIR / 2); idx += TPB) {
        int i2 = idx & 15, r = idx >> 4;
        sWposp[r][i2] = pk2(Wpos[r * PAIR + 2 * i2], Wpos[r * PAIR + 2 * i2 + 1]);
    }
    {   // left codes for this block's 8 n's: exactly 128 packed entries
        int nloc = t >> 4, i2 = t & 15;
        int n = blockIdx.x * 8 + nloc;
        sleft[nloc][i2] = pk2(g_left[n * PAIR + 2 * i2], g_left[n * PAIR + 2 * i2 + 1]);
    }
    if (t < PAIR / 2) { sln2[t] = pk2(lns[2 * t], lns[2 * t + 1]);
                        slnb2[t] = pk2(lnb[2 * t], lnb[2 * t + 1]); }
    if (t < BINS / 2) sb2p[t] = pk2(b2[2 * t], b2[2 * t + 1]);
    if (t < HID)      sb1[t] = b1[t];
    if (t < 8) { int2 m = g_meta[blockIdx.x * 8 + t];
                 sres[t] = m.x; skey[t] = m.y; }
    __syncthreads();

    const int pid0 = blockIdx.x * (TPB * PMUX) + t;
    int pid[PMUX], nb[PMUX];
    int2 mt[PMUX];
    u64 d2[PMUX][PAIR / 2];

    // ---- batched gathers: all LDGs in flight before any dependent compute ----
#pragma unroll
    for (int p = 0; p < PMUX; p++) {
        pid[p] = pid0 + p * TPB;
        nb[p]  = neigh[pid[p]];                   // coalesced
    }
#pragma unroll
    for (int p = 0; p < PMUX; p++) mt[p] = g_meta[nb[p]];   // one LDG.64
#pragma unroll
    for (int p = 0; p < PMUX; p++) {
        const ulonglong2* rrow = (const ulonglong2*)&g_right[(size_t)nb[p] * PAIR];
#pragma unroll
        for (int q = 0; q < 8; q++) {
            ulonglong2 v = rrow[q];               // L2-resident gather, 32 LDG.128 batched
            d2[p][2 * q] = v.x; d2[p][2 * q + 1] = v.y;
        }
    }

    // ---- combine + LayerNorm ----
#pragma unroll
    for (int p = 0; p < PMUX; p++) {
        const int nloc = (t + p * TPB) >> 6;      // 0..7
#pragma unroll
        for (int i = 0; i < PAIR / 2; i++) d2[p][i] = f2add(d2[p][i], sleft[nloc][i]);

        int dr = mt[p].x - sres[nloc];
        dr = min(max(dr, -CLIPV), CLIPV) + CLIPV;
        if (mt[p].y == skey[nloc]) {
#pragma unroll
            for (int i = 0; i < PAIR / 2; i++) d2[p][i] = f2add(d2[p][i], sWposp[dr][i]);
        }

        u64 s2 = d2[p][0];
#pragma unroll
        for (int i = 1; i < PAIR / 2; i++) s2 = f2add(s2, d2[p][i]);
        float2 sf = upk2(s2);
        const float mu = (sf.x + sf.y) * (1.0f / PAIR);
        const u64 nmu2 = pk2(-mu, -mu);
        u64 v2 = 0;
#pragma unroll
        for (int i = 0; i < PAIR / 2; i++) {
            u64 e = f2add(d2[p][i], nmu2);
            v2 = f2fma(e, e, v2);
            d2[p][i] = e;
        }
        float2 vf = upk2(v2);
        const float rs = rsqrtf((vf.x + vf.y) * (1.0f / PAIR) + LN_EPS);
        const u64 rs2 = pk2(rs, rs);
#pragma unroll
        for (int i = 0; i < PAIR / 2; i++)
            d2[p][i] = f2fma(f2mul(d2[p][i], rs2), sln2[i], slnb2[i]);
    }

    // ---- MLP: 32 -> 64 (gelu via MUFU.TANH) -> 16, packed FFMA2 ----
    u64 lg2[PMUX][BINS / 2];
#pragma unroll
    for (int p = 0; p < PMUX; p++)
#pragma unroll
        for (int b = 0; b < BINS / 2; b++) lg2[p][b] = sb2p[b];

#pragma unroll 4
    for (int j = 0; j < HID; j++) {
        const u64 bj2 = pk2(sb1[j], 0.0f);        // bias folded into accumulator
        u64 acc[PMUX] = {bj2, bj2, bj2, bj2};
        const ulonglong2* w1r = (const ulonglong2*)sW1p[j];
#pragma unroll
        for (int q = 0; q < 8; q++) {
            ulonglong2 w = w1r[q];                // broadcast LDS.128, pre-packed
#pragma unroll
            for (int p = 0; p < PMUX; p++) {
                acc[p] = f2fma(d2[p][2 * q], w.x, acc[p]);
                acc[p] = f2fma(d2[p][2 * q + 1], w.y, acc[p]);
            }
        }
        u64 hp[PMUX];
#pragma unroll
        for (int p = 0; p < PMUX; p++) {
            float2 af = upk2(acc[p]);
            float a = af.x + af.y;
            // 2*gelu(a) = a(1+tanh(0.7978845608(a + 0.044715 a^3))); 0.5 is in W2
            float x2 = a * a;
            float u  = a * fmaf(0.0356774081f, x2, 0.7978845608f);
            float th = tanh_approx(u);            // single MUFU op
            float h  = fmaf(a, th, a);            // = 2*gelu(a)
            hp[p] = pk2(h, h);
        }
        const ulonglong2* w2r = (const ulonglong2*)sW2p[j];
#pragma unroll
        for (int q = 0; q < 4; q++) {
            ulonglong2 w = w2r[q];                // broadcast LDS.128, pre-halved
#pragma unroll
            for (int p = 0; p < PMUX; p++) {
                lg2[p][2 * q]     = f2fma(hp[p], w.x, lg2[p][2 * q]);
                lg2[p][2 * q + 1] = f2fma(hp[p], w.y, lg2[p][2 * q + 1]);
            }
        }
    }

    // ---- log_softmax + expected distance + store (streaming) ----
#pragma unroll
    for (int p = 0; p < PMUX; p++) {
        float l[BINS];
#pragma unroll
        for (int b = 0; b < BINS / 2; b++) {
            float2 f = upk2(lg2[p][b]);
            l[2 * b] = f.x; l[2 * b + 1] = f.y;
        }
        float m = l[0];
#pragma unroll
        for (int b = 1; b < BINS; b++) m = fmaxf(m, l[b]);
        const float mm = -m * LOG2E;
        float s = 0.0f, ws = 0.0f;
#pragma unroll
        for (int b = 0; b < BINS; b++) {
            float e = ex2f(fmaf(l[b], LOG2E, mm));   // exp(l-m) via one MUFU
            s += e;
            ws = fmaf(e, ((float)b + 0.5f) * 1.375f, ws);
        }
        const float ofs = m + __logf(s);

        float* op = out_logp + (size_t)pid[p] * BINS;
#pragma unroll
        for (int b4 = 0; b4 < BINS / 4; b4++) {
            float4 o;
            o.x = l[b4 * 4 + 0] - ofs;
            o.y = l[b4 * 4 + 1] - ofs;
            o.z = l[b4 * 4 + 2] - ofs;
            o.w = l[b4 * 4 + 3] - ofs;
            __stcs((float4*)(op + b4 * 4), o);    // streaming: don't pollute L2
        }
        __stcs(out_dmap + pid[p], __fdividef(ws, s));
    }
}

// ---------------------------------------------------------------------------
extern "C" void kernel_launch(void* const* d_in, const int* in_sizes, int n_in,
                              void* d_out, int out_size)
{
    const float* feat  = (const float*)d_in[0];
    const int*   resi  = (const int*)  d_in[1];
    const int*   chain = (const int*)  d_in[2];
    const int*   batch = (const int*)  d_in[3];
    const int*   neigh = (const int*)  d_in[4];
    const float* Wl    = (const float*)d_in[5];
    const float* Wr    = (const float*)d_in[6];
    const float* Wpos  = (const float*)d_in[7];
    const float* lns   = (const float*)d_in[8];
    const float* lnb   = (const float*)d_in[9];
    const float* W1    = (const float*)d_in[10];
    const float* b1    = (const float*)d_in[11];
    const float* W2    = (const float*)d_in[12];
    const float* b2    = (const float*)d_in[13];

    float* out_logp = (float*)d_out;
    float* out_dmap = (float*)d_out + (size_t)NPTS * KNB * BINS;

    meta_kernel<<<NPTS / 256, 256>>>(resi, chain, batch);
    proj_kernel<<<NPTS / 64, 256>>>(feat, Wl, Wr);
    pair_kernel<<<(NPTS * KNB) / (TPB * PMUX), TPB>>>(neigh, Wpos, lns, lnb,
                                                      W1, b1, W2, b2,
                                                      out_logp, out_dmap);
}

// round 9
// speedup vs baseline: 1.7408x; 1.0156x over previous
#include <cuda_runtime.h>

#define NPTS 32768
#define KNB  64
#define CDIM 256
#define PAIR 32
#define HID  64
#define BINS 16
#define CLIPV 32
#define LN_EPS 1e-5f
#define PMUX 4            // pairs per thread
#define TPB  128          // threads per block -> 512 pairs = 8 n's per block
#define LOG2E 1.4426950408889634f

typedef unsigned long long u64;

// Scratch (allocation-free rule -> __device__ globals)
static __device__ float g_left[NPTS * PAIR];    // 4 MB
static __device__ float g_right[NPTS * PAIR];   // 4 MB
static __device__ int2  g_meta[NPTS];           // (resi, chain<<16|batch)

// ---------------- packed f32x2 helpers (FFMA2: PTX-only on sm_103a) --------
__device__ __forceinline__ u64 pk2(float lo, float hi) {
    u64 r; asm("mov.b64 %0,{%1,%2};" : "=l"(r) : "f"(lo), "f"(hi)); return r;
}
__device__ __forceinline__ float2 upk2(u64 v) {
    float2 f; asm("mov.b64 {%0,%1},%2;" : "=f"(f.x), "=f"(f.y) : "l"(v)); return f;
}
__device__ __forceinline__ u64 f2fma(u64 a, u64 b, u64 c) {
    u64 r; asm("fma.rn.f32x2 %0,%1,%2,%3;" : "=l"(r) : "l"(a), "l"(b), "l"(c)); return r;
}
__device__ __forceinline__ u64 f2add(u64 a, u64 b) {
    u64 r; asm("add.rn.f32x2 %0,%1,%2;" : "=l"(r) : "l"(a), "l"(b)); return r;
}
__device__ __forceinline__ u64 f2mul(u64 a, u64 b) {
    u64 r; asm("mul.rn.f32x2 %0,%1,%2;" : "=l"(r) : "l"(a), "l"(b)); return r;
}
__device__ __forceinline__ float tanh_approx(float x) {
    float r; asm("tanh.approx.f32 %0,%1;" : "=f"(r) : "f"(x)); return r;
}
__device__ __forceinline__ float ex2f(float x) {
    float r; asm("ex2.approx.f32 %0,%1;" : "=f"(r) : "f"(x)); return r;
}

// ---------------------------------------------------------------------------
// Kernel 0: pack per-residue metadata into one 8-byte record
// ---------------------------------------------------------------------------
__global__ __launch_bounds__(256) void meta_kernel(
    const int* __restrict__ resi,
    const int* __restrict__ chain,
    const int* __restrict__ batch)
{
    int i = blockIdx.x * 256 + threadIdx.x;
    g_meta[i] = make_int2(resi[i], (chain[i] << 16) | batch[i]);
}

// ---------------------------------------------------------------------------
// Kernel 1: left = feat @ W_left, right = feat @ W_right  (fused as 64 cols)
// ---------------------------------------------------------------------------
__global__ __launch_bounds__(256) void proj_kernel(
    const float* __restrict__ feat,
    const float* __restrict__ Wl,
    const float* __restrict__ Wr)
{
    __shared__ float As[32][68];
    __shared__ float Bs[32][64];

    const int t   = threadIdx.x;
    const int tx  = t & 15;
    const int ty  = t >> 4;
    const int row0 = blockIdx.x * 64;

    float acc[4][4];
#pragma unroll
    for (int i = 0; i < 4; i++)
#pragma unroll
        for (int j = 0; j < 4; j++) acc[i][j] = 0.0f;

    const int lc   = t & 31;
    const int lr   = t >> 5;
    const int bcol = t & 63;
    const int bk0  = t >> 6;

    for (int cb = 0; cb < CDIM; cb += 32) {
#pragma unroll
        for (int it = 0; it < 8; it++)
            As[lc][lr + it * 8] = feat[(size_t)(row0 + lr + it * 8) * CDIM + cb + lc];
#pragma unroll
        for (int it = 0; it < 8; it++) {
            int kk = bk0 + it * 4;
            Bs[kk][bcol] = (bcol < PAIR) ? Wl[(cb + kk) * PAIR + bcol]
                                         : Wr[(cb + kk) * PAIR + (bcol - PAIR)];
        }
        __syncthreads();
#pragma unroll
        for (int kk = 0; kk < 32; kk++) {
            float4 a4 = *(const float4*)&As[kk][ty * 4];
            float4 b4 = *(const float4*)&Bs[kk][tx * 4];
            float av[4] = {a4.x, a4.y, a4.z, a4.w};
            float bv[4] = {b4.x, b4.y, b4.z, b4.w};
#pragma unroll
            for (int i = 0; i < 4; i++)
#pragma unroll
                for (int j = 0; j < 4; j++)
                    acc[i][j] = fmaf(av[i], bv[j], acc[i][j]);
        }
        __syncthreads();
    }

#pragma unroll
    for (int i = 0; i < 4; i++) {
        int row = row0 + ty * 4 + i;
#pragma unroll
        for (int j = 0; j < 4; j++) {
            int col = tx * 4 + j;
            if (col < PAIR) g_left[row * PAIR + col] = acc[i][j];
            else            g_right[row * PAIR + (col - PAIR)] = acc[i][j];
        }
    }
}

// ---------------------------------------------------------------------------
// Kernel 2: per-pair pipeline, 4 pairs/thread, packed f32x2 math.
// 2 hidden units per iteration with deferred gelu: long FFMA2 runs,
// 8-wide MUFU batches, fewer stall points.
// ---------------------------------------------------------------------------
__global__ __launch_bounds__(TPB, 2) void pair_kernel(
    const int*   __restrict__ neigh,
    const float* __restrict__ Wpos,
    const float* __restrict__ lns,
    const float* __restrict__ lnb,
    const float* __restrict__ W1,
    const float* __restrict__ b1,
    const float* __restrict__ W2,
    const float* __restrict__ b2,
    float* __restrict__ out_logp,
    float* __restrict__ out_dmap)
{
    __shared__ __align__(16) u64 sW1p[HID][PAIR / 2];          // [j][i2], transposed, packed
    __shared__ __align__(16) u64 sW2p[HID][BINS / 2];          // [j][b2], packed, pre-halved
    __shared__ __align__(16) u64 sWposp[2 * CLIPV + 1][PAIR / 2];
    __shared__ __align__(16) u64 sleft[8][PAIR / 2];
    __shared__ u64 sln2[PAIR / 2], slnb2[PAIR / 2], sb2p[BINS / 2];
    __shared__ float sb1[HID];
    __shared__ int sres[8], skey[8];

    const int t = threadIdx.x;

    for (int idx = t; idx < HID * (PAIR / 2); idx += TPB) {
        int i2 = idx & 15, j = idx >> 4;
        sW1p[j][i2] = pk2(W1[(2 * i2) * HID + j], W1[(2 * i2 + 1) * HID + j]);
    }
    for (int idx = t; idx < HID * (BINS / 2); idx += TPB) {
        int b2i = idx & 7, j = idx >> 3;
        sW2p[j][b2i] = pk2(0.5f * W2[j * BINS + 2 * b2i],
                           0.5f * W2[j * BINS + 2 * b2i + 1]);   // 0.5 of gelu folded in
    }
    for (int idx = t; idx < (2 * CLIPV + 1) * (PAIR / 2); idx += TPB) {
        int i2 = idx & 15, r = idx >> 4;
        sWposp[r][i2] = pk2(Wpos[r * PAIR + 2 * i2], Wpos[r * PAIR + 2 * i2 + 1]);
    }
    {   // left codes for this block's 8 n's: exactly 128 packed entries
        int nloc = t >> 4, i2 = t & 15;
        int n = blockIdx.x * 8 + nloc;
        sleft[nloc][i2] = pk2(g_left[n * PAIR + 2 * i2], g_left[n * PAIR + 2 * i2 + 1]);
    }
    if (t < PAIR / 2) { sln2[t] = pk2(lns[2 * t], lns[2 * t + 1]);
                        slnb2[t] = pk2(lnb[2 * t], lnb[2 * t + 1]); }
    if (t < BINS / 2) sb2p[t] = pk2(b2[2 * t], b2[2 * t + 1]);
    if (t < HID)      sb1[t] = b1[t];
    if (t < 8) { int2 m = g_meta[blockIdx.x * 8 + t];
                 sres[t] = m.x; skey[t] = m.y; }
    __syncthreads();

    const int pid0 = blockIdx.x * (TPB * PMUX) + t;
    int nb[PMUX];
    int2 mt[PMUX];
    u64 d2[PMUX][PAIR / 2];

    // ---- batched gathers: all LDGs in flight before any dependent compute ----
#pragma unroll
    for (int p = 0; p < PMUX; p++) nb[p] = neigh[pid0 + p * TPB];   // coalesced
#pragma unroll
    for (int p = 0; p < PMUX; p++) mt[p] = g_meta[nb[p]];           // one LDG.64
#pragma unroll
    for (int p = 0; p < PMUX; p++) {
        const ulonglong2* rrow = (const ulonglong2*)&g_right[(size_t)nb[p] * PAIR];
#pragma unroll
        for (int q = 0; q < 8; q++) {
            ulonglong2 v = rrow[q];               // L2-resident gather, 32 LDG.128 batched
            d2[p][2 * q] = v.x; d2[p][2 * q + 1] = v.y;
        }
    }

    // ---- combine + LayerNorm ----
#pragma unroll
    for (int p = 0; p < PMUX; p++) {
        const int nloc = (t + p * TPB) >> 6;      // 0..7
#pragma unroll
        for (int i = 0; i < PAIR / 2; i++) d2[p][i] = f2add(d2[p][i], sleft[nloc][i]);

        int dr = mt[p].x - sres[nloc];
        dr = min(max(dr, -CLIPV), CLIPV) + CLIPV;
        if (mt[p].y == skey[nloc]) {
#pragma unroll
            for (int i = 0; i < PAIR / 2; i++) d2[p][i] = f2add(d2[p][i], sWposp[dr][i]);
        }

        u64 s2 = d2[p][0];
#pragma unroll
        for (int i = 1; i < PAIR / 2; i++) s2 = f2add(s2, d2[p][i]);
        float2 sf = upk2(s2);
        const float mu = (sf.x + sf.y) * (1.0f / PAIR);
        const u64 nmu2 = pk2(-mu, -mu);
        u64 v2 = 0;
#pragma unroll
        for (int i = 0; i < PAIR / 2; i++) {
            u64 e = f2add(d2[p][i], nmu2);
            v2 = f2fma(e, e, v2);
            d2[p][i] = e;
        }
        float2 vf = upk2(v2);
        const float rs = rsqrtf((vf.x + vf.y) * (1.0f / PAIR) + LN_EPS);
        const u64 rs2 = pk2(rs, rs);
#pragma unroll
        for (int i = 0; i < PAIR / 2; i++)
            d2[p][i] = f2fma(f2mul(d2[p][i], rs2), sln2[i], slnb2[i]);
    }

    // ---- MLP: 2 hidden units per iteration, deferred gelu ----
    u64 lg2[PMUX][BINS / 2];
#pragma unroll
    for (int p = 0; p < PMUX; p++)
#pragma unroll
        for (int b = 0; b < BINS / 2; b++) lg2[p][b] = sb2p[b];

#pragma unroll 2
    for (int jj = 0; jj < HID; jj += 2) {
        float a0[PMUX], a1[PMUX];

        // W1 dot for j = jj  (64 FFMA2, 4 independent chains)
        {
            const u64 bj2 = pk2(sb1[jj], 0.0f);
            u64 acc[PMUX] = {bj2, bj2, bj2, bj2};
            const ulonglong2* w1r = (const ulonglong2*)sW1p[jj];
#pragma unroll
            for (int q = 0; q < 8; q++) {
                ulonglong2 w = w1r[q];
#pragma unroll
                for (int p = 0; p < PMUX; p++) {
                    acc[p] = f2fma(d2[p][2 * q], w.x, acc[p]);
                    acc[p] = f2fma(d2[p][2 * q + 1], w.y, acc[p]);
                }
            }
#pragma unroll
            for (int p = 0; p < PMUX; p++) { float2 f = upk2(acc[p]); a0[p] = f.x + f.y; }
        }
        // W1 dot for j = jj+1 (runs back-to-back: ~128-FFMA2 window)
        {
            const u64 bj2 = pk2(sb1[jj + 1], 0.0f);
            u64 acc[PMUX] = {bj2, bj2, bj2, bj2};
            const ulonglong2* w1r = (const ulonglong2*)sW1p[jj + 1];
#pragma unroll
            for (int q = 0; q < 8; q++) {
                ulonglong2 w = w1r[q];
#pragma unroll
                for (int p = 0; p < PMUX; p++) {
                    acc[p] = f2fma(d2[p][2 * q], w.x, acc[p]);
                    acc[p] = f2fma(d2[p][2 * q + 1], w.y, acc[p]);
                }
            }
#pragma unroll
            for (int p = 0; p < PMUX; p++) { float2 f = upk2(acc[p]); a1[p] = f.x + f.y; }
        }

        // 8-wide batched gelu: 2*gelu(a) = a(1+tanh(c1 a + c3 a^3)); 0.5 in W2
        u64 h0[PMUX], h1[PMUX];
#pragma unroll
        for (int p = 0; p < PMUX; p++) {
            float aA = a0[p], aB = a1[p];
            float uA = aA * fmaf(0.0356774081f, aA * aA, 0.7978845608f);
            float uB = aB * fmaf(0.0356774081f, aB * aB, 0.7978845608f);
            float tA = tanh_approx(uA);
            float tB = tanh_approx(uB);
            float hA = fmaf(aA, tA, aA);
            float hB = fmaf(aB, tB, aB);
            h0[p] = pk2(hA, hA);
            h1[p] = pk2(hB, hB);
        }

        // W2 accumulate for both j (64 FFMA2 run)
        {
            const ulonglong2* w2a = (const ulonglong2*)sW2p[jj];
            const ulonglong2* w2b = (const ulonglong2*)sW2p[jj + 1];
#pragma unroll
            for (int q = 0; q < 4; q++) {
                ulonglong2 wa = w2a[q];
                ulonglong2 wb = w2b[q];
#pragma unroll
                for (int p = 0; p < PMUX; p++) {
                    lg2[p][2 * q]     = f2fma(h0[p], wa.x, lg2[p][2 * q]);
                    lg2[p][2 * q + 1] = f2fma(h0[p], wa.y, lg2[p][2 * q + 1]);
                }
#pragma unroll
                for (int p = 0; p < PMUX; p++) {
                    lg2[p][2 * q]     = f2fma(h1[p], wb.x, lg2[p][2 * q]);
                    lg2[p][2 * q + 1] = f2fma(h1[p], wb.y, lg2[p][2 * q + 1]);
                }
            }
        }
    }

    // ---- log_softmax + expected distance + store (streaming) ----
#pragma unroll
    for (int p = 0; p < PMUX; p++) {
        float l[BINS];
#pragma unroll
        for (int b = 0; b < BINS / 2; b++) {
            float2 f = upk2(lg2[p][b]);
            l[2 * b] = f.x; l[2 * b + 1] = f.y;
        }
        float m = l[0];
#pragma unroll
        for (int b = 1; b < BINS; b++) m = fmaxf(m, l[b]);
        const float mm = -m * LOG2E;
        float s = 0.0f, ws = 0.0f;
#pragma unroll
        for (int b = 0; b < BINS; b++) {
            float e = ex2f(fmaf(l[b], LOG2E, mm));   // exp(l-m) via one MUFU
            s += e;
            ws = fmaf(e, ((float)b + 0.5f) * 1.375f, ws);
        }
        const float ofs = m + __logf(s);

        float* op = out_logp + (size_t)(pid0 + p * TPB) * BINS;
#pragma unroll
        for (int b4 = 0; b4 < BINS / 4; b4++) {
            float4 o;
            o.x = l[b4 * 4 + 0] - ofs;
            o.y = l[b4 * 4 + 1] - ofs;
            o.z = l[b4 * 4 + 2] - ofs;
            o.w = l[b4 * 4 + 3] - ofs;
            __stcs((float4*)(op + b4 * 4), o);    // streaming: don't pollute L2
        }
        __stcs(out_dmap + pid0 + p * TPB, __fdividef(ws, s));
    }
}

// ---------------------------------------------------------------------------
extern "C" void kernel_launch(void* const* d_in, const int* in_sizes, int n_in,
                              void* d_out, int out_size)
{
    const float* feat  = (const float*)d_in[0];
    const int*   resi  = (const int*)  d_in[1];
    const int*   chain = (const int*)  d_in[2];
    const int*   batch = (const int*)  d_in[3];
    const int*   neigh = (const int*)  d_in[4];
    const float* Wl    = (const float*)d_in[5];
    const float* Wr    = (const float*)d_in[6];
    const float* Wpos  = (const float*)d_in[7];
    const float* lns   = (const float*)d_in[8];
    const float* lnb   = (const float*)d_in[9];
    const float* W1    = (const float*)d_in[10];
    const float* b1    = (const float*)d_in[11];
    const float* W2    = (const float*)d_in[12];
    const float* b2    = (const float*)d_in[13];

    float* out_logp = (float*)d_out;
    float* out_dmap = (float*)d_out + (size_t)NPTS * KNB * BINS;

    meta_kernel<<<NPTS / 256, 256>>>(resi, chain, batch);
    proj_kernel<<<NPTS / 64, 256>>>(feat, Wl, Wr);
    pair_kernel<<<(NPTS * KNB) / (TPB * PMUX), TPB>>>(neigh, Wpos, lns, lnb,
                                                      W1, b1, W2, b2,
                                                      out_logp, out_dmap);
}